// round 2
// baseline (speedup 1.0000x reference)
#include <cuda_runtime.h>

// GRU-ODE: B=32768 rows, T=28, DIM=H=32, 10-step RK4, RHS = 2-layer tanh MLP.
// 4 threads per row (8 components each): ~48 live floats/thread -> fully
// register-resident (fixes R1 local-mem blowup). Operand exchange via
// width-4 warp shuffles; weights TRANSPOSED in smem so each quad lane's
// float4 read lands on distinct bank groups (conflict-free broadcast).

#define TT 28
#define NSTEPS 10

struct __align__(16) SW {
    float T1[1024];        // T1[k*32+j] = W1[j*32+k]
    float T2[1024];
    float Tih[3][1024];    // per-gate transposed blocks
    float Thh[3][1024];
    float b1[32], b2[32];
    float bih[96], bhh[96];
};

__device__ __forceinline__ float sigmoidf_fast(float x) {
    return __fdividef(1.0f, 1.0f + __expf(-x));
}
__device__ __forceinline__ float tanhf_fast(float x) {
    // tanh(x) = 1 - 2/(1+e^{2x}); well-behaved at +/-inf under approx rcp.
    return 1.0f - __fdividef(2.0f, 1.0f + __expf(2.0f * x));
}

// acc[j'] += sum_k y_k * T[k*32 + qoff + j'], y distributed 8/thread across
// the 4-lane quad. 32 SHFL + 64 LDS.128-bytes worth + 256 FMA per thread.
__device__ __forceinline__ void mv32q(const float* __restrict__ T, int qoff,
                                      const float (&y)[8], float (&acc)[8]) {
#pragma unroll
    for (int src = 0; src < 4; ++src) {
#pragma unroll
        for (int m = 0; m < 8; ++m) {
            const int k = src * 8 + m;
            const float yk = __shfl_sync(0xffffffffu, y[m], src, 4);
            const float4 wa = *reinterpret_cast<const float4*>(T + k * 32 + qoff);
            const float4 wb = *reinterpret_cast<const float4*>(T + k * 32 + qoff + 4);
            acc[0] = fmaf(yk, wa.x, acc[0]);
            acc[1] = fmaf(yk, wa.y, acc[1]);
            acc[2] = fmaf(yk, wa.z, acc[2]);
            acc[3] = fmaf(yk, wa.w, acc[3]);
            acc[4] = fmaf(yk, wb.x, acc[4]);
            acc[5] = fmaf(yk, wb.y, acc[5]);
            acc[6] = fmaf(yk, wb.z, acc[6]);
            acc[7] = fmaf(yk, wb.w, acc[7]);
        }
    }
}

// f = tanh(y @ W1^T + b1) @ W2^T + b2   (this thread's 8-component slice)
__device__ __forceinline__ void rhs(const SW* __restrict__ s, int qoff,
                                    const float (&b1q)[8], const float (&b2q)[8],
                                    const float (&y)[8], float (&f)[8]) {
    float z[8];
#pragma unroll
    for (int j = 0; j < 8; ++j) z[j] = b1q[j];
    mv32q(s->T1, qoff, y, z);
#pragma unroll
    for (int j = 0; j < 8; ++j) z[j] = tanhf_fast(z[j]);
#pragma unroll
    for (int j = 0; j < 8; ++j) f[j] = b2q[j];
    mv32q(s->T2, qoff, z, f);
}

__device__ __forceinline__ void rk4(const SW* __restrict__ s, int qoff,
                                    const float (&b1q)[8], const float (&b2q)[8],
                                    float (&h)[8], float span) {
    const float dt = span * (1.0f / NSTEPS);
#pragma unroll 1
    for (int st = 0; st < NSTEPS; ++st) {
        float yt[8], ks[8], kc[8];
#pragma unroll
        for (int j = 0; j < 8; ++j) { yt[j] = h[j]; ks[j] = 0.0f; }
#pragma unroll 1
        for (int sg = 0; sg < 4; ++sg) {
            rhs(s, qoff, b1q, b2q, yt, kc);
            const float ws = (sg == 1 || sg == 2) ? 2.0f : 1.0f;
            const float cn = (sg < 2) ? 0.5f * dt : dt;
#pragma unroll
            for (int j = 0; j < 8; ++j) {
                ks[j] = fmaf(ws, kc[j], ks[j]);
                yt[j] = fmaf(cn, kc[j], h[j]);   // harmless extra at sg=3
            }
        }
#pragma unroll
        for (int j = 0; j < 8; ++j) h[j] = fmaf(dt * (1.0f / 6.0f), ks[j], h[j]);
    }
}

// PyTorch gate order r,z,n
__device__ __forceinline__ void gru(const SW* __restrict__ s, int qoff,
                                    float (&h)[8], const float (&x)[8]) {
    float gr[8], gz[8], gn[8], gh[8];
#pragma unroll
    for (int j = 0; j < 8; ++j) {
        gr[j] = s->bih[qoff + j]      + s->bhh[qoff + j];
        gz[j] = s->bih[32 + qoff + j] + s->bhh[32 + qoff + j];
        gn[j] = s->bih[64 + qoff + j];
        gh[j] = s->bhh[64 + qoff + j];
    }
    mv32q(s->Tih[0], qoff, x, gr);
    mv32q(s->Thh[0], qoff, h, gr);
    mv32q(s->Tih[1], qoff, x, gz);
    mv32q(s->Thh[1], qoff, h, gz);
    mv32q(s->Tih[2], qoff, x, gn);
    mv32q(s->Thh[2], qoff, h, gh);
#pragma unroll
    for (int j = 0; j < 8; ++j) {
        const float r = sigmoidf_fast(gr[j]);
        const float z = sigmoidf_fast(gz[j]);
        const float n = tanhf_fast(gn[j] + r * gh[j]);
        h[j] = n + z * (h[j] - n);   // (1-z)*n + z*h
    }
}

extern "C" __global__ void __launch_bounds__(256)
ode_gru_kernel(const float* __restrict__ inputs, const float* __restrict__ h0,
               const float* __restrict__ Wih, const float* __restrict__ Whh,
               const float* __restrict__ bih, const float* __restrict__ bhh,
               const float* __restrict__ W1, const float* __restrict__ b1,
               const float* __restrict__ W2, const float* __restrict__ b2,
               float* __restrict__ out, int B) {
    __shared__ SW s;
    for (int i = threadIdx.x; i < 1024; i += blockDim.x) {
        const int j = i >> 5, k = i & 31;
        s.T1[k * 32 + j] = W1[i];
        s.T2[k * 32 + j] = W2[i];
    }
    for (int i = threadIdx.x; i < 3072; i += blockDim.x) {
        const int g = i >> 10, r = (i >> 5) & 31, k = i & 31;  // Wih[(g*32+r)*32+k]
        s.Tih[g][k * 32 + r] = Wih[i];
        s.Thh[g][k * 32 + r] = Whh[i];
    }
    for (int i = threadIdx.x; i < 32; i += blockDim.x) { s.b1[i] = b1[i]; s.b2[i] = b2[i]; }
    for (int i = threadIdx.x; i < 96; i += blockDim.x) { s.bih[i] = bih[i]; s.bhh[i] = bhh[i]; }
    __syncthreads();

    const int gt  = blockIdx.x * blockDim.x + threadIdx.x;
    const int row = gt >> 2;
    const int qoff = (gt & 3) * 8;
    if (row >= B) return;   // B=32768: uniform per warp

    float b1q[8], b2q[8];
#pragma unroll
    for (int j = 0; j < 8; ++j) { b1q[j] = s.b1[qoff + j]; b2q[j] = s.b2[qoff + j]; }

    float h[8];
    {
        const float4 a = *reinterpret_cast<const float4*>(h0 + (size_t)row * 32 + qoff);
        const float4 b = *reinterpret_cast<const float4*>(h0 + (size_t)row * 32 + qoff + 4);
        h[0] = a.x; h[1] = a.y; h[2] = a.z; h[3] = a.w;
        h[4] = b.x; h[5] = b.y; h[6] = b.z; h[7] = b.w;
    }

    const float* xb = inputs + (size_t)row * TT * 32 + qoff;

    // initial integration over [0, 1]
    rk4(&s, qoff, b1q, b2q, h, 1.0f);

#pragma unroll 1
    for (int t = 0; t < TT; ++t) {
        float x[8];
        const float4 a = *reinterpret_cast<const float4*>(xb + t * 32);
        const float4 b = *reinterpret_cast<const float4*>(xb + t * 32 + 4);
        x[0] = a.x; x[1] = a.y; x[2] = a.z; x[3] = a.w;
        x[4] = b.x; x[5] = b.y; x[6] = b.z; x[7] = b.w;
        gru(&s, qoff, h, x);
        if (t < TT - 1) rk4(&s, qoff, b1q, b2q, h, 1.0f);
    }

    // after last GRU: h_start -> out[0], then 14-unit integration -> out[1]
    {
        float* o0 = out + (size_t)row * 32 + qoff;
#pragma unroll
        for (int j = 0; j < 8; ++j) o0[j] = fmaxf(h[j], 0.0f);
    }
    rk4(&s, qoff, b1q, b2q, h, 14.0f);
    {
        float* o1 = out + (size_t)B * 32 + (size_t)row * 32 + qoff;
#pragma unroll
        for (int j = 0; j < 8; ++j) o1[j] = fmaxf(h[j], 0.0f);
    }
}

extern "C" void kernel_launch(void* const* d_in, const int* in_sizes, int n_in,
                              void* d_out, int out_size) {
    const float* inputs = (const float*)d_in[0];
    const float* h0     = (const float*)d_in[1];
    const float* Wih    = (const float*)d_in[2];
    const float* Whh    = (const float*)d_in[3];
    const float* bih    = (const float*)d_in[4];
    const float* bhh    = (const float*)d_in[5];
    const float* W1     = (const float*)d_in[6];
    const float* b1     = (const float*)d_in[7];
    const float* W2     = (const float*)d_in[8];
    const float* b2     = (const float*)d_in[9];

    const int B = in_sizes[1] / 32;       // h0 is [B, 32]
    const int threads = 256;
    const long total = (long)B * 4;
    const int blocks = (int)((total + threads - 1) / threads);
    ode_gru_kernel<<<blocks, threads>>>(inputs, h0, Wih, Whh, bih, bhh,
                                        W1, b1, W2, b2, (float*)d_out, B);
}

// round 3
// speedup vs baseline: 1.6769x; 1.6769x over previous
#include <cuda_runtime.h>

// GRU-ODE: B=32768 rows, T=28, DIM=H=32, 10-step RK4, RHS = 2-layer tanh MLP.
// 4 threads per row-pair (8 components each, 2 rows per thread). Weight LDS is
// shared across both rows: per k-iter 2 LDS.128 + 2 SHFL feed 16 FMA, making
// the fp32 FMA pipe (not MIO) the binder. Weights TRANSPOSED in smem so each
// quad lane's float4 read is conflict-free broadcast.

#define TT 28
#define NSTEPS 10

struct __align__(16) SW {
    float T1[1024];        // T1[k*32+j] = W1[j*32+k]
    float T2[1024];
    float Tih[3][1024];    // per-gate transposed blocks
    float Thh[3][1024];
    float b1[32], b2[32];
    float bih[96], bhh[96];
};

__device__ __forceinline__ float sigmoidf_fast(float x) {
    return __fdividef(1.0f, 1.0f + __expf(-x));
}
__device__ __forceinline__ float tanhf_fast(float x) {
    // tanh(x) = 1 - 2/(1+e^{2x}); well-behaved at +/-inf under approx rcp.
    return 1.0f - __fdividef(2.0f, 1.0f + __expf(2.0f * x));
}

// acc[r][j'] += sum_k y[r]_k * T[k*32 + qoff + j'] for r in {0,1}.
// One weight load pair serves both rows: 2 LDS.128 + 2 SHFL -> 16 FMA.
__device__ __forceinline__ void mv32q2(const float* __restrict__ T, int qoff,
                                       const float (&y)[2][8], float (&acc)[2][8]) {
#pragma unroll
    for (int src = 0; src < 4; ++src) {
#pragma unroll
        for (int m = 0; m < 8; ++m) {
            const int k = src * 8 + m;
            const float ya = __shfl_sync(0xffffffffu, y[0][m], src, 4);
            const float yb = __shfl_sync(0xffffffffu, y[1][m], src, 4);
            const float4 wa = *reinterpret_cast<const float4*>(T + k * 32 + qoff);
            const float4 wb = *reinterpret_cast<const float4*>(T + k * 32 + qoff + 4);
            acc[0][0] = fmaf(ya, wa.x, acc[0][0]);
            acc[0][1] = fmaf(ya, wa.y, acc[0][1]);
            acc[0][2] = fmaf(ya, wa.z, acc[0][2]);
            acc[0][3] = fmaf(ya, wa.w, acc[0][3]);
            acc[0][4] = fmaf(ya, wb.x, acc[0][4]);
            acc[0][5] = fmaf(ya, wb.y, acc[0][5]);
            acc[0][6] = fmaf(ya, wb.z, acc[0][6]);
            acc[0][7] = fmaf(ya, wb.w, acc[0][7]);
            acc[1][0] = fmaf(yb, wa.x, acc[1][0]);
            acc[1][1] = fmaf(yb, wa.y, acc[1][1]);
            acc[1][2] = fmaf(yb, wa.z, acc[1][2]);
            acc[1][3] = fmaf(yb, wa.w, acc[1][3]);
            acc[1][4] = fmaf(yb, wb.x, acc[1][4]);
            acc[1][5] = fmaf(yb, wb.y, acc[1][5]);
            acc[1][6] = fmaf(yb, wb.z, acc[1][6]);
            acc[1][7] = fmaf(yb, wb.w, acc[1][7]);
        }
    }
}

// f = tanh(y @ W1^T + b1) @ W2^T + b2   (both rows' 8-component slices)
__device__ __forceinline__ void rhs(const SW* __restrict__ s, int qoff,
                                    const float (&b1q)[8], const float (&b2q)[8],
                                    const float (&y)[2][8], float (&f)[2][8]) {
    float z[2][8];
#pragma unroll
    for (int r = 0; r < 2; ++r)
#pragma unroll
        for (int j = 0; j < 8; ++j) z[r][j] = b1q[j];
    mv32q2(s->T1, qoff, y, z);
#pragma unroll
    for (int r = 0; r < 2; ++r)
#pragma unroll
        for (int j = 0; j < 8; ++j) z[r][j] = tanhf_fast(z[r][j]);
#pragma unroll
    for (int r = 0; r < 2; ++r)
#pragma unroll
        for (int j = 0; j < 8; ++j) f[r][j] = b2q[j];
    mv32q2(s->T2, qoff, z, f);
}

__device__ __forceinline__ void rk4(const SW* __restrict__ s, int qoff,
                                    const float (&b1q)[8], const float (&b2q)[8],
                                    float (&h)[2][8], float span) {
    const float dt = span * (1.0f / NSTEPS);
#pragma unroll 1
    for (int st = 0; st < NSTEPS; ++st) {
        float yt[2][8], ks[2][8], kc[2][8];
#pragma unroll
        for (int r = 0; r < 2; ++r)
#pragma unroll
            for (int j = 0; j < 8; ++j) { yt[r][j] = h[r][j]; ks[r][j] = 0.0f; }
#pragma unroll 1
        for (int sg = 0; sg < 4; ++sg) {
            rhs(s, qoff, b1q, b2q, yt, kc);
            const float ws = (sg == 1 || sg == 2) ? 2.0f : 1.0f;
            const float cn = (sg < 2) ? 0.5f * dt : dt;
#pragma unroll
            for (int r = 0; r < 2; ++r)
#pragma unroll
                for (int j = 0; j < 8; ++j) {
                    ks[r][j] = fmaf(ws, kc[r][j], ks[r][j]);
                    yt[r][j] = fmaf(cn, kc[r][j], h[r][j]);  // harmless extra at sg=3
                }
        }
#pragma unroll
        for (int r = 0; r < 2; ++r)
#pragma unroll
            for (int j = 0; j < 8; ++j)
                h[r][j] = fmaf(dt * (1.0f / 6.0f), ks[r][j], h[r][j]);
    }
}

// PyTorch gate order r,z,n
__device__ __forceinline__ void gru(const SW* __restrict__ s, int qoff,
                                    float (&h)[2][8], const float (&x)[2][8]) {
    float gr[2][8], gz[2][8], gn[2][8], gh[2][8];
#pragma unroll
    for (int r = 0; r < 2; ++r)
#pragma unroll
        for (int j = 0; j < 8; ++j) {
            gr[r][j] = s->bih[qoff + j]      + s->bhh[qoff + j];
            gz[r][j] = s->bih[32 + qoff + j] + s->bhh[32 + qoff + j];
            gn[r][j] = s->bih[64 + qoff + j];
            gh[r][j] = s->bhh[64 + qoff + j];
        }
    mv32q2(s->Tih[0], qoff, x, gr);
    mv32q2(s->Thh[0], qoff, h, gr);
    mv32q2(s->Tih[1], qoff, x, gz);
    mv32q2(s->Thh[1], qoff, h, gz);
    mv32q2(s->Tih[2], qoff, x, gn);
    mv32q2(s->Thh[2], qoff, h, gh);
#pragma unroll
    for (int r = 0; r < 2; ++r)
#pragma unroll
        for (int j = 0; j < 8; ++j) {
            const float rr = sigmoidf_fast(gr[r][j]);
            const float zz = sigmoidf_fast(gz[r][j]);
            const float nn = tanhf_fast(gn[r][j] + rr * gh[r][j]);
            h[r][j] = nn + zz * (h[r][j] - nn);   // (1-z)*n + z*h
        }
}

__device__ __forceinline__ void load8(const float* __restrict__ p, float (&v)[8]) {
    const float4 a = *reinterpret_cast<const float4*>(p);
    const float4 b = *reinterpret_cast<const float4*>(p + 4);
    v[0] = a.x; v[1] = a.y; v[2] = a.z; v[3] = a.w;
    v[4] = b.x; v[5] = b.y; v[6] = b.z; v[7] = b.w;
}

extern "C" __global__ void __launch_bounds__(128)
ode_gru_kernel(const float* __restrict__ inputs, const float* __restrict__ h0,
               const float* __restrict__ Wih, const float* __restrict__ Whh,
               const float* __restrict__ bih, const float* __restrict__ bhh,
               const float* __restrict__ W1, const float* __restrict__ b1,
               const float* __restrict__ W2, const float* __restrict__ b2,
               float* __restrict__ out, int B) {
    __shared__ SW s;
    for (int i = threadIdx.x; i < 1024; i += blockDim.x) {
        const int j = i >> 5, k = i & 31;
        s.T1[k * 32 + j] = W1[i];
        s.T2[k * 32 + j] = W2[i];
    }
    for (int i = threadIdx.x; i < 3072; i += blockDim.x) {
        const int g = i >> 10, r = (i >> 5) & 31, k = i & 31;  // Wih[(g*32+r)*32+k]
        s.Tih[g][k * 32 + r] = Wih[i];
        s.Thh[g][k * 32 + r] = Whh[i];
    }
    for (int i = threadIdx.x; i < 32; i += blockDim.x) { s.b1[i] = b1[i]; s.b2[i] = b2[i]; }
    for (int i = threadIdx.x; i < 96; i += blockDim.x) { s.bih[i] = bih[i]; s.bhh[i] = bhh[i]; }
    __syncthreads();

    const int gt   = blockIdx.x * blockDim.x + threadIdx.x;
    const int pair = gt >> 2;            // row-pair index
    const int qoff = (gt & 3) * 8;
    const int rowA = pair * 2;
    const int rowB = rowA + 1;
    if (rowB >= B) return;   // B even: uniform per warp

    float b1q[8], b2q[8];
#pragma unroll
    for (int j = 0; j < 8; ++j) { b1q[j] = s.b1[qoff + j]; b2q[j] = s.b2[qoff + j]; }

    float h[2][8];
    load8(h0 + (size_t)rowA * 32 + qoff, h[0]);
    load8(h0 + (size_t)rowB * 32 + qoff, h[1]);

    const float* xa = inputs + (size_t)rowA * TT * 32 + qoff;
    const float* xbp = inputs + (size_t)rowB * TT * 32 + qoff;

    // initial integration over [0, 1]
    rk4(&s, qoff, b1q, b2q, h, 1.0f);

#pragma unroll 1
    for (int t = 0; t < TT; ++t) {
        float x[2][8];
        load8(xa + t * 32, x[0]);
        load8(xbp + t * 32, x[1]);
        gru(&s, qoff, h, x);
        if (t < TT - 1) rk4(&s, qoff, b1q, b2q, h, 1.0f);
    }

    // after last GRU: h_start -> out[0], then 14-unit integration -> out[1]
#pragma unroll
    for (int j = 0; j < 8; ++j) {
        out[(size_t)rowA * 32 + qoff + j] = fmaxf(h[0][j], 0.0f);
        out[(size_t)rowB * 32 + qoff + j] = fmaxf(h[1][j], 0.0f);
    }
    rk4(&s, qoff, b1q, b2q, h, 14.0f);
#pragma unroll
    for (int j = 0; j < 8; ++j) {
        out[(size_t)B * 32 + (size_t)rowA * 32 + qoff + j] = fmaxf(h[0][j], 0.0f);
        out[(size_t)B * 32 + (size_t)rowB * 32 + qoff + j] = fmaxf(h[1][j], 0.0f);
    }
}

extern "C" void kernel_launch(void* const* d_in, const int* in_sizes, int n_in,
                              void* d_out, int out_size) {
    const float* inputs = (const float*)d_in[0];
    const float* h0     = (const float*)d_in[1];
    const float* Wih    = (const float*)d_in[2];
    const float* Whh    = (const float*)d_in[3];
    const float* bih    = (const float*)d_in[4];
    const float* bhh    = (const float*)d_in[5];
    const float* W1     = (const float*)d_in[6];
    const float* b1     = (const float*)d_in[7];
    const float* W2     = (const float*)d_in[8];
    const float* b2     = (const float*)d_in[9];

    const int B = in_sizes[1] / 32;       // h0 is [B, 32]
    const int threads = 128;
    const long total = ((long)B / 2) * 4; // 4 threads per row-pair
    const int blocks = (int)((total + threads - 1) / threads);
    ode_gru_kernel<<<blocks, threads>>>(inputs, h0, Wih, Whh, bih, bhh,
                                        W1, b1, W2, b2, (float*)d_out, B);
}

// round 4
// speedup vs baseline: 1.7545x; 1.0463x over previous
#include <cuda_runtime.h>

// GRU-ODE: B=32768 rows, T=28, DIM=H=32, 10-step RK4, RHS = 2-layer tanh MLP.
// 4 threads per 4-row group (quad): each thread owns 8 output components (j)
// of 4 rows. Accumulators packed as f32x2 along j (fma.rn.f32x2, PTX-only);
// weights arrive naturally packed via LDS.128 of the transposed smem matrix;
// multiplier = 1-MOV splat (ALU pipe, idle) of the width-4-shuffled y scalar.
// Per k-iter/thread: 2 LDS.128 + 4 SHFL + 4 MOV + 16 FFMA2 => 32 FMA-ops.

#define TT 28
#define NSTEPS 10
typedef unsigned long long u64;

struct __align__(16) SW {
    float T1[1024], T2[1024];       // T[k*32+j] = W[j*32+k] (transposed)
    float Tih[3][1024], Thh[3][1024];
    float b1[32], b2[32];
    float br[32], bz[32], bni[32], bnh[32];  // GRU biases (r,z presummed)
};

__device__ __forceinline__ u64 splat2(float x) {
    u64 d; asm("mov.b64 %0, {%1, %1};" : "=l"(d) : "f"(x)); return d;
}
__device__ __forceinline__ float2 unpack2(u64 v) {
    float2 r; asm("mov.b64 {%0, %1}, %2;" : "=f"(r.x), "=f"(r.y) : "l"(v)); return r;
}
__device__ __forceinline__ u64 fma2(u64 a, u64 b, u64 c) {
    u64 d; asm("fma.rn.f32x2 %0, %1, %2, %3;" : "=l"(d) : "l"(a), "l"(b), "l"(c)); return d;
}

__device__ __forceinline__ float sigmoidf_fast(float x) {
    return __fdividef(1.0f, 1.0f + __expf(-x));
}
__device__ __forceinline__ float tanhf_fast(float x) {
    return 1.0f - __fdividef(2.0f, 1.0f + __expf(2.0f * x));
}

// acc[r][p] (f32x2 pair over j=(2p,2p+1)) += y[r][k] * T[k*32+qoff+j] over k.
template <int R>
__device__ __forceinline__ void mvR(const float* __restrict__ T, int qoff,
                                    const float (&y)[R][8], u64 (&a)[R][4]) {
#pragma unroll
    for (int src = 0; src < 4; ++src) {
#pragma unroll
        for (int m = 0; m < 8; ++m) {
            const int k = src * 8 + m;
            const ulonglong2 wlo = *reinterpret_cast<const ulonglong2*>(T + k * 32 + qoff);
            const ulonglong2 whi = *reinterpret_cast<const ulonglong2*>(T + k * 32 + qoff + 4);
#pragma unroll
            for (int r = 0; r < R; ++r) {
                const u64 s = splat2(__shfl_sync(0xffffffffu, y[r][m], src, 4));
                a[r][0] = fma2(s, wlo.x, a[r][0]);
                a[r][1] = fma2(s, wlo.y, a[r][1]);
                a[r][2] = fma2(s, whi.x, a[r][2]);
                a[r][3] = fma2(s, whi.y, a[r][3]);
            }
        }
    }
}

// f = tanh(y @ W1^T + b1) @ W2^T + b2 for 4 rows (this thread's 8-j slice).
__device__ __forceinline__ void rhs4(const SW* __restrict__ s, int qoff,
                                     const float (&y)[4][8], float (&f)[4][8]) {
    u64 acc[4][4];
#pragma unroll
    for (int p = 0; p < 4; ++p) {
        const u64 b = *reinterpret_cast<const u64*>(s->b1 + qoff + 2 * p);
#pragma unroll
        for (int r = 0; r < 4; ++r) acc[r][p] = b;
    }
    mvR<4>(s->T1, qoff, y, acc);
    float z[4][8];
#pragma unroll
    for (int r = 0; r < 4; ++r)
#pragma unroll
        for (int p = 0; p < 4; ++p) {
            const float2 v = unpack2(acc[r][p]);
            z[r][2 * p]     = tanhf_fast(v.x);
            z[r][2 * p + 1] = tanhf_fast(v.y);
        }
#pragma unroll
    for (int p = 0; p < 4; ++p) {
        const u64 b = *reinterpret_cast<const u64*>(s->b2 + qoff + 2 * p);
#pragma unroll
        for (int r = 0; r < 4; ++r) acc[r][p] = b;
    }
    mvR<4>(s->T2, qoff, z, acc);
#pragma unroll
    for (int r = 0; r < 4; ++r)
#pragma unroll
        for (int p = 0; p < 4; ++p) {
            const float2 v = unpack2(acc[r][p]);
            f[r][2 * p] = v.x; f[r][2 * p + 1] = v.y;
        }
}

__device__ __forceinline__ void rk4(const SW* __restrict__ s, int qoff,
                                    float (&h)[4][8], float span) {
    const float dt = span * (1.0f / NSTEPS);
#pragma unroll 1
    for (int st = 0; st < NSTEPS; ++st) {
        float yt[4][8], ks[4][8], kc[4][8];
#pragma unroll
        for (int r = 0; r < 4; ++r)
#pragma unroll
            for (int j = 0; j < 8; ++j) { yt[r][j] = h[r][j]; ks[r][j] = 0.0f; }
#pragma unroll 1
        for (int sg = 0; sg < 4; ++sg) {
            rhs4(s, qoff, yt, kc);
            const float ws = (sg == 1 || sg == 2) ? 2.0f : 1.0f;
            const float cn = (sg < 2) ? 0.5f * dt : dt;
#pragma unroll
            for (int r = 0; r < 4; ++r)
#pragma unroll
                for (int j = 0; j < 8; ++j) {
                    ks[r][j] = fmaf(ws, kc[r][j], ks[r][j]);
                    yt[r][j] = fmaf(cn, kc[r][j], h[r][j]);   // extra at sg=3: harmless
                }
        }
#pragma unroll
        for (int r = 0; r < 4; ++r)
#pragma unroll
            for (int j = 0; j < 8; ++j)
                h[r][j] = fmaf(dt * (1.0f / 6.0f), ks[r][j], h[r][j]);
    }
}

// PyTorch-order GRU (r,z,n) on 2 rows (keeps live set bounded; GRU is ~2% of work).
__device__ __forceinline__ void gru2(const SW* __restrict__ s, int qoff,
                                     float (&h)[2][8], const float (&x)[2][8]) {
    u64 a1[2][4], a2[2][4];
    float rg[2][8], zg[2][8];
    // r gate
#pragma unroll
    for (int p = 0; p < 4; ++p) {
        const u64 b = *reinterpret_cast<const u64*>(s->br + qoff + 2 * p);
        a1[0][p] = b; a1[1][p] = b;
    }
    mvR<2>(s->Tih[0], qoff, x, a1);
    mvR<2>(s->Thh[0], qoff, h, a1);
#pragma unroll
    for (int r = 0; r < 2; ++r)
#pragma unroll
        for (int p = 0; p < 4; ++p) {
            const float2 v = unpack2(a1[r][p]);
            rg[r][2 * p]     = sigmoidf_fast(v.x);
            rg[r][2 * p + 1] = sigmoidf_fast(v.y);
        }
    // z gate
#pragma unroll
    for (int p = 0; p < 4; ++p) {
        const u64 b = *reinterpret_cast<const u64*>(s->bz + qoff + 2 * p);
        a1[0][p] = b; a1[1][p] = b;
    }
    mvR<2>(s->Tih[1], qoff, x, a1);
    mvR<2>(s->Thh[1], qoff, h, a1);
#pragma unroll
    for (int r = 0; r < 2; ++r)
#pragma unroll
        for (int p = 0; p < 4; ++p) {
            const float2 v = unpack2(a1[r][p]);
            zg[r][2 * p]     = sigmoidf_fast(v.x);
            zg[r][2 * p + 1] = sigmoidf_fast(v.y);
        }
    // n gate: gin (input part) and ghn (hidden part) separately
#pragma unroll
    for (int p = 0; p < 4; ++p) {
        const u64 bi = *reinterpret_cast<const u64*>(s->bni + qoff + 2 * p);
        const u64 bh = *reinterpret_cast<const u64*>(s->bnh + qoff + 2 * p);
        a1[0][p] = bi; a1[1][p] = bi;
        a2[0][p] = bh; a2[1][p] = bh;
    }
    mvR<2>(s->Tih[2], qoff, x, a1);
    mvR<2>(s->Thh[2], qoff, h, a2);
#pragma unroll
    for (int r = 0; r < 2; ++r)
#pragma unroll
        for (int p = 0; p < 4; ++p) {
            const float2 gi = unpack2(a1[r][p]);
            const float2 gh = unpack2(a2[r][p]);
            const float n0 = tanhf_fast(gi.x + rg[r][2 * p] * gh.x);
            const float n1 = tanhf_fast(gi.y + rg[r][2 * p + 1] * gh.y);
            h[r][2 * p]     = n0 + zg[r][2 * p]     * (h[r][2 * p]     - n0);
            h[r][2 * p + 1] = n1 + zg[r][2 * p + 1] * (h[r][2 * p + 1] - n1);
        }
}

__device__ __forceinline__ void load8(const float* __restrict__ p, float (&v)[8]) {
    const float4 a = *reinterpret_cast<const float4*>(p);
    const float4 b = *reinterpret_cast<const float4*>(p + 4);
    v[0] = a.x; v[1] = a.y; v[2] = a.z; v[3] = a.w;
    v[4] = b.x; v[5] = b.y; v[6] = b.z; v[7] = b.w;
}

extern "C" __global__ void __launch_bounds__(128)
ode_gru_kernel(const float* __restrict__ inputs, const float* __restrict__ h0,
               const float* __restrict__ Wih, const float* __restrict__ Whh,
               const float* __restrict__ bih, const float* __restrict__ bhh,
               const float* __restrict__ W1, const float* __restrict__ b1,
               const float* __restrict__ W2, const float* __restrict__ b2,
               float* __restrict__ out, int B) {
    __shared__ SW s;
    for (int i = threadIdx.x; i < 1024; i += blockDim.x) {
        const int j = i >> 5, k = i & 31;
        s.T1[k * 32 + j] = W1[i];
        s.T2[k * 32 + j] = W2[i];
    }
    for (int i = threadIdx.x; i < 3072; i += blockDim.x) {
        const int g = i >> 10, r = (i >> 5) & 31, k = i & 31;
        s.Tih[g][k * 32 + r] = Wih[i];
        s.Thh[g][k * 32 + r] = Whh[i];
    }
    for (int i = threadIdx.x; i < 32; i += blockDim.x) {
        s.b1[i]  = b1[i];            s.b2[i]  = b2[i];
        s.br[i]  = bih[i] + bhh[i];  s.bz[i]  = bih[32 + i] + bhh[32 + i];
        s.bni[i] = bih[64 + i];      s.bnh[i] = bhh[64 + i];
    }
    __syncthreads();

    const int gt   = blockIdx.x * blockDim.x + threadIdx.x;
    const int quad = gt >> 2;            // 4-row group index
    const int qoff = (gt & 3) * 8;
    const int row0 = quad * 4;
    if (row0 >= B) return;               // B % 4 == 0: uniform per warp

    float h[4][8];
#pragma unroll
    for (int r = 0; r < 4; ++r) load8(h0 + (size_t)(row0 + r) * 32 + qoff, h[r]);

    const float* xb = inputs + (size_t)row0 * TT * 32 + qoff;

    // initial integration over [0, 1]
    rk4(&s, qoff, h, 1.0f);

    auto& h01 = *reinterpret_cast<float(*)[2][8]>(&h[0]);
    auto& h23 = *reinterpret_cast<float(*)[2][8]>(&h[2]);

#pragma unroll 1
    for (int t = 0; t < TT; ++t) {
        {
            float x[2][8];
            load8(xb + (size_t)0 * TT * 32 + t * 32, x[0]);
            load8(xb + (size_t)1 * TT * 32 + t * 32, x[1]);
            gru2(&s, qoff, h01, x);
        }
        {
            float x[2][8];
            load8(xb + (size_t)2 * TT * 32 + t * 32, x[0]);
            load8(xb + (size_t)3 * TT * 32 + t * 32, x[1]);
            gru2(&s, qoff, h23, x);
        }
        if (t < TT - 1) rk4(&s, qoff, h, 1.0f);
    }

    // h_start -> out[0], then 14-unit integration -> out[1]
#pragma unroll
    for (int r = 0; r < 4; ++r)
#pragma unroll
        for (int j = 0; j < 8; ++j)
            out[(size_t)(row0 + r) * 32 + qoff + j] = fmaxf(h[r][j], 0.0f);

    rk4(&s, qoff, h, 14.0f);
#pragma unroll
    for (int r = 0; r < 4; ++r)
#pragma unroll
        for (int j = 0; j < 8; ++j)
            out[(size_t)B * 32 + (size_t)(row0 + r) * 32 + qoff + j] = fmaxf(h[r][j], 0.0f);
}

extern "C" void kernel_launch(void* const* d_in, const int* in_sizes, int n_in,
                              void* d_out, int out_size) {
    const float* inputs = (const float*)d_in[0];
    const float* h0     = (const float*)d_in[1];
    const float* Wih    = (const float*)d_in[2];
    const float* Whh    = (const float*)d_in[3];
    const float* bih    = (const float*)d_in[4];
    const float* bhh    = (const float*)d_in[5];
    const float* W1     = (const float*)d_in[6];
    const float* b1     = (const float*)d_in[7];
    const float* W2     = (const float*)d_in[8];
    const float* b2     = (const float*)d_in[9];

    const int B = in_sizes[1] / 32;        // h0 is [B, 32]
    const int threads = 128;
    const long total = (long)B;            // 4 threads per 4-row group = B threads
    const int blocks = (int)((total + threads - 1) / threads);
    ode_gru_kernel<<<blocks, threads>>>(inputs, h0, Wih, Whh, bih, bhh,
                                        W1, b1, W2, b2, (float*)d_out, B);
}